// round 12
// baseline (speedup 1.0000x reference)
#include <cuda_runtime.h>

// ---------------------------------------------------------------------------
// RNN_32109175505717: 3-layer tanh RNN (B=4096, T=128, HID=64, F=14) + FC head
// R12: R11 layer-skew pipeline (jobs A=L0(s), B=L1(s-1), C=L2(s-2); 2 barriers
// per super-step) at 512 threads with UNCHANGED total mv traffic:
// tile J=8 x P=2, ksplit 8 = kch(warp) x kcl(lane); one shfl_xor(8) fold
// keeps red at 4 quadrants/job (smem stays 231.9 KB). 4 warps/SMSP hides the
// latency that ncu showed (occ 12.5%, issue 46.9%, no pipe saturated).
// ---------------------------------------------------------------------------

#define HID      64
#define F_IN     14
#define T_STEPS  128
#define ELEMS    32
#define NTHREADS 512
#define NBLOCKS  128
#define NSUPER   (T_STEPS + 2)

typedef unsigned long long ull;

// ---- float-region (weights [k][j], 68-float rows) -------------------------
#define WROW   68
#define WF_A   0                       // 80 rows: [Wih0(14); zero(2); Whh0(64)]
#define WF_B   (WF_A + 80*WROW)        // 128 rows: [Wih1; Whh1]
#define WF_C   (WF_B + 128*WROW)       // 128 rows: [Wih2; Whh2]
#define WF_END (WF_C + 128*WROW)       // 22848 floats
// ---- ull-region -----------------------------------------------------------
#define HROW   18
#define U_XS   (WF_END/2)              // 16 rows (14 used)
#define U_H0   (U_XS + 16*HROW)
#define U_H1   (U_H0 + 64*HROW)
#define U_H2   (U_H1 + 64*HROW)
#define U_RED  (U_H2 + 64*HROW)        // 12 quadrants x 1152 ull
#define RED_Q  1152
#define U_END  (U_RED + 12*RED_Q)      // 28992 ull = 231936 B
#define U_FCRED U_RED
#define SMEM_BYTES (U_END * 8)

// ---- f32x2 helpers --------------------------------------------------------
__device__ __forceinline__ ull pack2(float lo, float hi) {
    ull r; asm("mov.b64 %0, {%1, %2};" : "=l"(r) : "f"(lo), "f"(hi)); return r;
}
__device__ __forceinline__ void unpack2(ull v, float& lo, float& hi) {
    asm("mov.b64 {%0, %1}, %2;" : "=f"(lo), "=f"(hi) : "l"(v));
}
__device__ __forceinline__ ull fma2(ull a, ull b, ull c) {
    ull d; asm("fma.rn.f32x2 %0, %1, %2, %3;" : "=l"(d) : "l"(a), "l"(b), "l"(c));
    return d;
}
__device__ __forceinline__ ull add2(ull a, ull b) {
    ull d; asm("add.rn.f32x2 %0, %1, %2;" : "=l"(d) : "l"(a), "l"(b));
    return d;
}
__device__ __forceinline__ float fast_tanh(float x) {
    x = fminf(fmaxf(x, -12.0f), 12.0f);
    float e = __expf(x + x);
    return __fdividef(e - 1.0f, e + 1.0f);
}
__device__ __forceinline__ ull tanh2(ull v) {
    float a, b; unpack2(v, a, b);
    return pack2(fast_tanh(a), fast_tanh(b));
}

// ---- one k-row: 8j x 2 ep-ull --------------------------------------------
__device__ __forceinline__ void mv_one(const float* __restrict__ wf,
                                       const ull* __restrict__ hb,
                                       int k, int w8, int u2, ull a[8][2])
{
    ulonglong2 h = *reinterpret_cast<const ulonglong2*>(hb + k * HROW + u2);
    const float* wr = wf + k * WROW + w8;
    float4 wa = *reinterpret_cast<const float4*>(wr);
    float4 wb = *reinterpret_cast<const float4*>(wr + 4);
    ull p;
    p = pack2(wa.x, wa.x); a[0][0]=fma2(h.x,p,a[0][0]); a[0][1]=fma2(h.y,p,a[0][1]);
    p = pack2(wa.y, wa.y); a[1][0]=fma2(h.x,p,a[1][0]); a[1][1]=fma2(h.y,p,a[1][1]);
    p = pack2(wa.z, wa.z); a[2][0]=fma2(h.x,p,a[2][0]); a[2][1]=fma2(h.y,p,a[2][1]);
    p = pack2(wa.w, wa.w); a[3][0]=fma2(h.x,p,a[3][0]); a[3][1]=fma2(h.y,p,a[3][1]);
    p = pack2(wb.x, wb.x); a[4][0]=fma2(h.x,p,a[4][0]); a[4][1]=fma2(h.y,p,a[4][1]);
    p = pack2(wb.y, wb.y); a[5][0]=fma2(h.x,p,a[5][0]); a[5][1]=fma2(h.y,p,a[5][1]);
    p = pack2(wb.z, wb.z); a[6][0]=fma2(h.x,p,a[6][0]); a[6][1]=fma2(h.y,p,a[6][1]);
    p = pack2(wb.w, wb.w); a[7][0]=fma2(h.x,p,a[7][0]); a[7][1]=fma2(h.y,p,a[7][1]);
}

// fold kcl pairs (lanes differing in bit 3) and store to red quadrant
__device__ __forceinline__ void fold_store(ull a[8][2], ull* __restrict__ red,
                                           int qbase, int jqh8, int u2,
                                           bool do_sts)
{
#pragma unroll
    for (int jj = 0; jj < 8; ++jj) {
#pragma unroll
        for (int pp = 0; pp < 2; ++pp)
            a[jj][pp] = add2(a[jj][pp],
                             __shfl_xor_sync(0xffffffffu, a[jj][pp], 8));
    }
    if (do_sts) {
#pragma unroll
        for (int jj = 0; jj < 8; ++jj)
            *reinterpret_cast<ulonglong2*>(
                red + qbase + (jqh8 + jj) * HROW + u2) =
                make_ulonglong2(a[jj][0], a[jj][1]);
    }
}

__global__ void __launch_bounds__(NTHREADS, 1)
rnn_fused_kernel(const float* __restrict__ x,
                 const float* __restrict__ Wih0, const float* __restrict__ Whh0,
                 const float* __restrict__ bih0, const float* __restrict__ bhh0,
                 const float* __restrict__ Wih1, const float* __restrict__ Whh1,
                 const float* __restrict__ bih1, const float* __restrict__ bhh1,
                 const float* __restrict__ Wih2, const float* __restrict__ Whh2,
                 const float* __restrict__ bih2, const float* __restrict__ bhh2,
                 const float* __restrict__ fc1w, const float* __restrict__ fc1b,
                 const float* __restrict__ fc2w, const float* __restrict__ fc2b,
                 float* __restrict__ out)
{
    extern __shared__ ull smu[];
    float* smf = (float*)smu;
    const int tid = threadIdx.x;

    // ---- zero all smem ----
    {
        uint4* p4 = reinterpret_cast<uint4*>(smu);
        for (int i = tid; i < (int)(U_END / 2); i += NTHREADS)
            p4[i] = make_uint4(0, 0, 0, 0);
    }
    __syncthreads();

    // ---- stage weights [k][j] ----
    for (int idx = tid; idx < 64 * F_IN; idx += NTHREADS) {
        int j = idx / F_IN, f = idx - j * F_IN;
        smf[WF_A + f * WROW + j] = Wih0[idx];
    }
    for (int idx = tid; idx < 64 * 64; idx += NTHREADS) {
        int j = idx >> 6, k = idx & 63;
        smf[WF_A + (16 + k) * WROW + j] = Whh0[idx];
        smf[WF_B + k * WROW + j]        = Wih1[idx];
        smf[WF_B + (64 + k) * WROW + j] = Whh1[idx];
        smf[WF_C + k * WROW + j]        = Wih2[idx];
        smf[WF_C + (64 + k) * WROW + j] = Whh2[idx];
    }

    // ---- producer mapping: 16 warps = kch(2) x jqh(8); lane = kcl(4) x u(8)
    const int w    = tid >> 5;
    const int lane = tid & 31;
    const int kch  = w >> 3;             // 0,1
    const int jqh8 = (w & 7) * 8;        // j base
    const int kcl  = lane >> 3;          // 0..3
    const int u    = lane & 7;           // 0..7
    const int u2   = u * 2;
    const int kc   = kch * 4 + kcl;      // 0..7 ; k = kc + 8i
    const bool do_sts = ((kcl & 1) == 0);
    const int q    = kch * 2 + (kcl >> 1);   // 0..3

    // ---- finisher mapping (all 512 threads, 2 ull per job) ----
    const int fj = tid >> 3;             // 0..63
    const int fo = (tid & 7) * 2;
    const int fbase = fj * HROW + fo;

    const float bf0 = bih0[fj] + bhh0[fj];
    const float bf1 = bih1[fj] + bhh1[fj];
    const float bf2 = bih2[fj] + bhh2[fj];

    const float* xblk = x + (size_t)blockIdx.x * ELEMS * T_STEPS * F_IN;
    float* xs_f = (float*)(smu + U_XS);
    ull* red = smu + U_RED;
    ull* H0 = smu + U_H0; ull* H1 = smu + U_H1; ull* H2 = smu + U_H2;

    // x staging: one scalar per thread (448 < 512)
    const int xe = tid / F_IN, xf = tid - xe * F_IN;
    const bool xact = (tid < ELEMS * F_IN);

    if (xact) xs_f[xf * 36 + xe] = xblk[xe * (T_STEPS * F_IN) + xf];
    __syncthreads();

    for (int s = 0; s < NSUPER; ++s) {
        float xp = 0.0f;
        const bool xstage = (s <= T_STEPS - 2);
        if (xstage && xact)
            xp = xblk[xe * (T_STEPS * F_IN) + (s + 1) * F_IN + xf];

        // ============ MV phase: 3 independent jobs ============
        {   // job A: L0(t=s), 80 rows -> 10 iters
            ull a[8][2] = {};
#pragma unroll 5
            for (int i = 0; i < 10; ++i)
                mv_one(smf + WF_A, smu + U_XS, kc + 8 * i, jqh8, u2, a);
            fold_store(a, red, (0 * 4 + q) * RED_Q, jqh8, u2, do_sts);
        }
        {   // job B: L1(t=s-1), 128 rows -> 16 iters
            ull a[8][2] = {};
#pragma unroll 8
            for (int i = 0; i < 16; ++i)
                mv_one(smf + WF_B, H0, kc + 8 * i, jqh8, u2, a);
            fold_store(a, red, (1 * 4 + q) * RED_Q, jqh8, u2, do_sts);
        }
        {   // job C: L2(t=s-2), 128 rows -> 16 iters
            ull a[8][2] = {};
#pragma unroll 8
            for (int i = 0; i < 16; ++i)
                mv_one(smf + WF_C, H1, kc + 8 * i, jqh8, u2, a);
            fold_store(a, red, (2 * 4 + q) * RED_Q, jqh8, u2, do_sts);
        }
        __syncthreads();

        // ============ FINISH phase (all 512 threads) ============
        if (s <= T_STEPS - 1) {          // job A -> H0
            ull s0 = 0, s1 = 0;
#pragma unroll
            for (int qq = 0; qq < 4; ++qq) {
                ulonglong2 v = *reinterpret_cast<const ulonglong2*>(
                    red + qq * RED_Q + fbase);
                s0 = add2(s0, v.x); s1 = add2(s1, v.y);
            }
            ull bp = pack2(bf0, bf0);
            *reinterpret_cast<ulonglong2*>(H0 + fbase) =
                make_ulonglong2(tanh2(add2(s0, bp)), tanh2(add2(s1, bp)));
        }
        if (s >= 1 && s <= T_STEPS) {    // job B -> H1
            ull s0 = 0, s1 = 0;
#pragma unroll
            for (int qq = 0; qq < 4; ++qq) {
                ulonglong2 v = *reinterpret_cast<const ulonglong2*>(
                    red + (4 + qq) * RED_Q + fbase);
                s0 = add2(s0, v.x); s1 = add2(s1, v.y);
            }
            ull bp = pack2(bf1, bf1);
            *reinterpret_cast<ulonglong2*>(H1 + fbase) =
                make_ulonglong2(tanh2(add2(s0, bp)), tanh2(add2(s1, bp)));
        }
        if (s >= 2) {                    // job C -> H2
            ull s0 = 0, s1 = 0;
#pragma unroll
            for (int qq = 0; qq < 4; ++qq) {
                ulonglong2 v = *reinterpret_cast<const ulonglong2*>(
                    red + (8 + qq) * RED_Q + fbase);
                s0 = add2(s0, v.x); s1 = add2(s1, v.y);
            }
            ull bp = pack2(bf2, bf2);
            *reinterpret_cast<ulonglong2*>(H2 + fbase) =
                make_ulonglong2(tanh2(add2(s0, bp)), tanh2(add2(s1, bp)));
        }
        if (xstage && xact) xs_f[xf * 36 + xe] = xp;
        __syncthreads();
    }

    // ---- FC head on final h2 (H2 rows stride 36 f32) ----
    const float* h2f = (const float*)H2;
    float contrib = 0.0f;
    if (tid < 256) {
        int e  = tid >> 3;
        int mg = tid & 7;
#pragma unroll
        for (int mi = 0; mi < 4; ++mi) {
            int m = mg * 4 + mi;
            float sfc = fc1b[m];
#pragma unroll 16
            for (int k = 0; k < HID; ++k)
                sfc = fmaf(fc1w[m * HID + k], h2f[k * 36 + e], sfc);
            contrib = fmaf(fc2w[m], fmaxf(sfc, 0.0f), contrib);
        }
    }
    __syncthreads();                     // all reads of red/H2 complete
    if (tid < 256) {
        float* fred = (float*)(smu + U_FCRED);
        fred[tid] = contrib;
    }
    __syncthreads();
    if (tid < ELEMS) {
        float* fred = (float*)(smu + U_FCRED);
        float sfc = fc2b[0];
#pragma unroll
        for (int i = 0; i < 8; ++i) sfc += fred[tid * 8 + i];
        out[blockIdx.x * ELEMS + tid] = sfc;
    }
}

extern "C" void kernel_launch(void* const* d_in, const int* in_sizes, int n_in,
                              void* d_out, int out_size)
{
    const float* x    = (const float*)d_in[0];
    const float* Wih0 = (const float*)d_in[1];
    const float* Whh0 = (const float*)d_in[2];
    const float* bih0 = (const float*)d_in[3];
    const float* bhh0 = (const float*)d_in[4];
    const float* Wih1 = (const float*)d_in[5];
    const float* Whh1 = (const float*)d_in[6];
    const float* bih1 = (const float*)d_in[7];
    const float* bhh1 = (const float*)d_in[8];
    const float* Wih2 = (const float*)d_in[9];
    const float* Whh2 = (const float*)d_in[10];
    const float* bih2 = (const float*)d_in[11];
    const float* bhh2 = (const float*)d_in[12];
    const float* fc1w = (const float*)d_in[13];
    const float* fc1b = (const float*)d_in[14];
    const float* fc2w = (const float*)d_in[15];
    const float* fc2b = (const float*)d_in[16];
    float* out = (float*)d_out;

    cudaFuncSetAttribute(rnn_fused_kernel,
                         cudaFuncAttributeMaxDynamicSharedMemorySize, SMEM_BYTES);

    rnn_fused_kernel<<<NBLOCKS, NTHREADS, SMEM_BYTES>>>(
        x, Wih0, Whh0, bih0, bhh0,
        Wih1, Whh1, bih1, bhh1,
        Wih2, Whh2, bih2, bhh2,
        fc1w, fc1b, fc2w, fc2b, out);
}

// round 13
// speedup vs baseline: 1.2026x; 1.2026x over previous
#include <cuda_runtime.h>

// ---------------------------------------------------------------------------
// RNN_32109175505717: 3-layer tanh RNN (B=4096, T=128, HID=64, F=14) + FC head
// R13 = R11 (256 thr, layer-skew pipeline, 2 barriers/step, tile 8j x 4e,
// ksplit 4) with J-PAIR accumulators: f32x2 holds {j,j+1} so weights load as
// natural ull pairs (no per-weight pack); only h needs 1 pack per e.
// mv instr per k-row: 27 -> 23. Traffic / fma identical to R11.
// ---------------------------------------------------------------------------

#define HID      64
#define F_IN     14
#define T_STEPS  128
#define ELEMS    32
#define NTHREADS 256
#define NBLOCKS  128
#define NSUPER   (T_STEPS + 2)

typedef unsigned long long ull;

// ---- float-region (weights [k][j], 68-float rows) -------------------------
#define WROW   68
#define WF_A   0                       // 80 rows: [Wih0(14); zero(2); Whh0(64)]
#define WF_B   (WF_A + 80*WROW)        // 128 rows: [Wih1; Whh1]
#define WF_C   (WF_B + 128*WROW)       // 128 rows: [Wih2; Whh2]
#define WF_END (WF_C + 128*WROW)       // 22848 floats
// ---- ull-region -----------------------------------------------------------
// H rows: 36 f32 (=18 ull) per k-row. xs contiguous before H0 for job A.
#define U_XS   (WF_END/2)
#define U_H0   (U_XS + 16*18)
#define U_H1   (U_H0 + 64*18)
#define U_H2   (U_H1 + 64*18)
#define U_RED  (U_H2 + 64*18)          // 12 quadrants x [32 jp][36 ull]
#define RED_Q  1152
#define RED_ROW 36
#define U_END  (U_RED + 12*RED_Q)      // 231936 B
#define U_FCRED U_RED
#define SMEM_BYTES (U_END * 8)

// ---- f32x2 helpers --------------------------------------------------------
__device__ __forceinline__ ull pack2(float lo, float hi) {
    ull r; asm("mov.b64 %0, {%1, %2};" : "=l"(r) : "f"(lo), "f"(hi)); return r;
}
__device__ __forceinline__ void unpack2(ull v, float& lo, float& hi) {
    asm("mov.b64 {%0, %1}, %2;" : "=f"(lo), "=f"(hi) : "l"(v));
}
__device__ __forceinline__ ull fma2(ull a, ull b, ull c) {
    ull d; asm("fma.rn.f32x2 %0, %1, %2, %3;" : "=l"(d) : "l"(a), "l"(b), "l"(c));
    return d;
}
__device__ __forceinline__ ull add2(ull a, ull b) {
    ull d; asm("add.rn.f32x2 %0, %1, %2;" : "=l"(d) : "l"(a), "l"(b));
    return d;
}
__device__ __forceinline__ float fast_tanh(float x) {
    x = fminf(fmaxf(x, -12.0f), 12.0f);
    float e = __expf(x + x);
    return __fdividef(e - 1.0f, e + 1.0f);
}
__device__ __forceinline__ ull tanh2(ull v) {
    float a, b; unpack2(v, a, b);
    return pack2(fast_tanh(a), fast_tanh(b));
}

// ---- one k-row: 4 j-pairs x 4 e ------------------------------------------
// wf: [k][64j] f32 (stride WROW). hb: [k][36 f32] rows (h/x values, scalar).
__device__ __forceinline__ void mv_one(const float* __restrict__ wf,
                                       const float* __restrict__ hb,
                                       int k, int w8, int u4, ull a[4][4])
{
    float4 hv = *reinterpret_cast<const float4*>(hb + k * 36 + u4);
    const float* wr = wf + k * WROW + w8;
    ulonglong2 w01 = *reinterpret_cast<const ulonglong2*>(wr);      // jp0,jp1
    ulonglong2 w23 = *reinterpret_cast<const ulonglong2*>(wr + 4);  // jp2,jp3
    ull ph;
    ph = pack2(hv.x, hv.x);
    a[0][0]=fma2(w01.x,ph,a[0][0]); a[1][0]=fma2(w01.y,ph,a[1][0]);
    a[2][0]=fma2(w23.x,ph,a[2][0]); a[3][0]=fma2(w23.y,ph,a[3][0]);
    ph = pack2(hv.y, hv.y);
    a[0][1]=fma2(w01.x,ph,a[0][1]); a[1][1]=fma2(w01.y,ph,a[1][1]);
    a[2][1]=fma2(w23.x,ph,a[2][1]); a[3][1]=fma2(w23.y,ph,a[3][1]);
    ph = pack2(hv.z, hv.z);
    a[0][2]=fma2(w01.x,ph,a[0][2]); a[1][2]=fma2(w01.y,ph,a[1][2]);
    a[2][2]=fma2(w23.x,ph,a[2][2]); a[3][2]=fma2(w23.y,ph,a[3][2]);
    ph = pack2(hv.w, hv.w);
    a[0][3]=fma2(w01.x,ph,a[0][3]); a[1][3]=fma2(w01.y,ph,a[1][3]);
    a[2][3]=fma2(w23.x,ph,a[2][3]); a[3][3]=fma2(w23.y,ph,a[3][3]);
}

__global__ void __launch_bounds__(NTHREADS, 1)
rnn_fused_kernel(const float* __restrict__ x,
                 const float* __restrict__ Wih0, const float* __restrict__ Whh0,
                 const float* __restrict__ bih0, const float* __restrict__ bhh0,
                 const float* __restrict__ Wih1, const float* __restrict__ Whh1,
                 const float* __restrict__ bih1, const float* __restrict__ bhh1,
                 const float* __restrict__ Wih2, const float* __restrict__ Whh2,
                 const float* __restrict__ bih2, const float* __restrict__ bhh2,
                 const float* __restrict__ fc1w, const float* __restrict__ fc1b,
                 const float* __restrict__ fc2w, const float* __restrict__ fc2b,
                 float* __restrict__ out)
{
    extern __shared__ ull smu[];
    float* smf = (float*)smu;
    const int tid = threadIdx.x;

    // ---- zero all smem (pad rows / H / xs must be 0) ----
    {
        uint4* p4 = reinterpret_cast<uint4*>(smu);
        for (int i = tid; i < (int)(U_END / 2); i += NTHREADS)
            p4[i] = make_uint4(0, 0, 0, 0);
    }
    __syncthreads();

    // ---- stage weights [k][j] ----
    for (int idx = tid; idx < 64 * F_IN; idx += NTHREADS) {
        int j = idx / F_IN, f = idx - j * F_IN;
        smf[WF_A + f * WROW + j] = Wih0[idx];
    }
    for (int idx = tid; idx < 64 * 64; idx += NTHREADS) {
        int j = idx >> 6, k = idx & 63;
        smf[WF_A + (16 + k) * WROW + j] = Whh0[idx];
        smf[WF_B + k * WROW + j]        = Wih1[idx];
        smf[WF_B + (64 + k) * WROW + j] = Whh1[idx];
        smf[WF_C + k * WROW + j]        = Wih2[idx];
        smf[WF_C + (64 + k) * WROW + j] = Whh2[idx];
    }

    // ---- producer mapping: 8 warps = j-octet; lane = kc(4) x u(8) ----
    const int w    = tid >> 5;
    const int lane = tid & 31;
    const int kc   = lane >> 3;          // 0..3 (k = kc + 4i)
    const int u    = lane & 7;           // 0..7
    const int w8   = w * 8;              // j base
    const int wp4  = w * 4;              // jp base
    const int u4   = u * 4;              // e base (4 e's per thread)
    // red store cols: e=u4+ee -> col 2u+ee (ee<2), 16+2u+(ee-2) (ee>=2)
    const int scol = 2 * u;

    // ---- finisher mapping ----
    const int fjp = tid >> 3;            // 0..31 (j-pair)
    const int fu  = tid & 7;             // e's = 4*fu + 0..3
    const int fcol = 2 * fu;
    const int fj0 = 2 * fjp;

    // bias pairs in registers
    const ull bf0 = pack2(bih0[fj0] + bhh0[fj0], bih0[fj0+1] + bhh0[fj0+1]);
    const ull bf1 = pack2(bih1[fj0] + bhh1[fj0], bih1[fj0+1] + bhh1[fj0+1]);
    const ull bf2 = pack2(bih2[fj0] + bhh2[fj0], bih2[fj0+1] + bhh2[fj0+1]);

    const float* xblk = x + (size_t)blockIdx.x * ELEMS * T_STEPS * F_IN;
    float* xs_f = (float*)(smu + U_XS);          // row f stride 36 f32
    ull* red = smu + U_RED;
    float* H0f = (float*)(smu + U_H0);
    float* H1f = (float*)(smu + U_H1);
    float* H2f = (float*)(smu + U_H2);

    // x staging: two scalars per thread (448 total)
    const int xe0 = tid / F_IN,  xf0 = tid - xe0 * F_IN;
    const int xi1 = tid + NTHREADS;
    const int xe1 = xi1 / F_IN,  xf1 = xi1 - xe1 * F_IN;
    const bool xa1 = (xi1 < ELEMS * F_IN);

    xs_f[xf0 * 36 + xe0] = xblk[xe0 * (T_STEPS * F_IN) + xf0];
    if (xa1) xs_f[xf1 * 36 + xe1] = xblk[xe1 * (T_STEPS * F_IN) + xf1];
    __syncthreads();

    for (int s = 0; s < NSUPER; ++s) {
        float xp0 = 0.0f, xp1 = 0.0f;
        const bool xstage = (s <= T_STEPS - 2);
        if (xstage) {
            xp0 = xblk[xe0 * (T_STEPS * F_IN) + (s + 1) * F_IN + xf0];
            if (xa1) xp1 = xblk[xe1 * (T_STEPS * F_IN) + (s + 1) * F_IN + xf1];
        }

        // ============ MV phase: 3 independent jobs ============
        {   // job A: L0(t=s) over [xs(16); H0] x W_A (80 rows)
            ull a[4][4] = {};
#pragma unroll 5
            for (int i = 0; i < 20; ++i)
                mv_one(smf + WF_A, xs_f, kc + 4 * i, w8, u4, a);
#pragma unroll
            for (int jj = 0; jj < 4; ++jj) {
                ull* rp = red + (0 * 4 + kc) * RED_Q + (wp4 + jj) * RED_ROW;
                *reinterpret_cast<ulonglong2*>(rp + scol) =
                    make_ulonglong2(a[jj][0], a[jj][1]);
                *reinterpret_cast<ulonglong2*>(rp + 16 + scol) =
                    make_ulonglong2(a[jj][2], a[jj][3]);
            }
        }
        {   // job B: L1(t=s-1) over [H0; H1] x W_B (128 rows)
            ull a[4][4] = {};
#pragma unroll 8
            for (int i = 0; i < 32; ++i)
                mv_one(smf + WF_B, H0f, kc + 4 * i, w8, u4, a);
#pragma unroll
            for (int jj = 0; jj < 4; ++jj) {
                ull* rp = red + (1 * 4 + kc) * RED_Q + (wp4 + jj) * RED_ROW;
                *reinterpret_cast<ulonglong2*>(rp + scol) =
                    make_ulonglong2(a[jj][0], a[jj][1]);
                *reinterpret_cast<ulonglong2*>(rp + 16 + scol) =
                    make_ulonglong2(a[jj][2], a[jj][3]);
            }
        }
        {   // job C: L2(t=s-2) over [H1; H2] x W_C (128 rows)
            ull a[4][4] = {};
#pragma unroll 8
            for (int i = 0; i < 32; ++i)
                mv_one(smf + WF_C, H1f, kc + 4 * i, w8, u4, a);
#pragma unroll
            for (int jj = 0; jj < 4; ++jj) {
                ull* rp = red + (2 * 4 + kc) * RED_Q + (wp4 + jj) * RED_ROW;
                *reinterpret_cast<ulonglong2*>(rp + scol) =
                    make_ulonglong2(a[jj][0], a[jj][1]);
                *reinterpret_cast<ulonglong2*>(rp + 16 + scol) =
                    make_ulonglong2(a[jj][2], a[jj][3]);
            }
        }
        __syncthreads();

        // ============ FINISH phase ============
        // res ull = {h[j0], h[j0+1]} for e = 4*fu + ee
#pragma unroll
        for (int L = 0; L < 3; ++L) {
            bool valid = (L == 0) ? (s <= T_STEPS - 1)
                       : (L == 1) ? (s >= 1 && s <= T_STEPS)
                                  : (s >= 2);
            if (!valid) continue;
            ull s0 = 0, s1 = 0, s2 = 0, s3 = 0;
#pragma unroll
            for (int q = 0; q < 4; ++q) {
                const ull* rp = red + (L * 4 + q) * RED_Q + fjp * RED_ROW;
                ulonglong2 va = *reinterpret_cast<const ulonglong2*>(rp + fcol);
                ulonglong2 vb = *reinterpret_cast<const ulonglong2*>(rp + 16 + fcol);
                s0 = add2(s0, va.x); s1 = add2(s1, va.y);
                s2 = add2(s2, vb.x); s3 = add2(s3, vb.y);
            }
            ull bp = (L == 0) ? bf0 : (L == 1) ? bf1 : bf2;
            float* Hf = (L == 0) ? H0f : (L == 1) ? H1f : H2f;
            ull r0 = tanh2(add2(s0, bp));
            ull r1 = tanh2(add2(s1, bp));
            ull r2 = tanh2(add2(s2, bp));
            ull r3 = tanh2(add2(s3, bp));
            float lo, hi;
            int e0 = 4 * fu;
            unpack2(r0, lo, hi);
            Hf[fj0 * 36 + e0]           = lo; Hf[(fj0 + 1) * 36 + e0]     = hi;
            unpack2(r1, lo, hi);
            Hf[fj0 * 36 + e0 + 1]       = lo; Hf[(fj0 + 1) * 36 + e0 + 1] = hi;
            unpack2(r2, lo, hi);
            Hf[fj0 * 36 + e0 + 2]       = lo; Hf[(fj0 + 1) * 36 + e0 + 2] = hi;
            unpack2(r3, lo, hi);
            Hf[fj0 * 36 + e0 + 3]       = lo; Hf[(fj0 + 1) * 36 + e0 + 3] = hi;
        }
        if (xstage) {
            xs_f[xf0 * 36 + xe0] = xp0;
            if (xa1) xs_f[xf1 * 36 + xe1] = xp1;
        }
        __syncthreads();
    }

    // ---- FC head on final h2 (H2 rows stride 36 f32) ----
    {
        int e  = tid >> 3;
        int mg = tid & 7;
        float contrib = 0.0f;
#pragma unroll
        for (int mi = 0; mi < 4; ++mi) {
            int m = mg * 4 + mi;
            float sfc = fc1b[m];
#pragma unroll 16
            for (int k = 0; k < HID; ++k)
                sfc = fmaf(fc1w[m * HID + k], H2f[k * 36 + e], sfc);
            contrib = fmaf(fc2w[m], fmaxf(sfc, 0.0f), contrib);
        }
        __syncthreads();                    // red reads done; reuse region
        float* fred = (float*)(smu + U_FCRED);
        fred[tid] = contrib;
    }
    __syncthreads();
    if (tid < ELEMS) {
        float* fred = (float*)(smu + U_FCRED);
        float sfc = fc2b[0];
#pragma unroll
        for (int i = 0; i < 8; ++i) sfc += fred[tid * 8 + i];
        out[blockIdx.x * ELEMS + tid] = sfc;
    }
}

extern "C" void kernel_launch(void* const* d_in, const int* in_sizes, int n_in,
                              void* d_out, int out_size)
{
    const float* x    = (const float*)d_in[0];
    const float* Wih0 = (const float*)d_in[1];
    const float* Whh0 = (const float*)d_in[2];
    const float* bih0 = (const float*)d_in[3];
    const float* bhh0 = (const float*)d_in[4];
    const float* Wih1 = (const float*)d_in[5];
    const float* Whh1 = (const float*)d_in[6];
    const float* bih1 = (const float*)d_in[7];
    const float* bhh1 = (const float*)d_in[8];
    const float* Wih2 = (const float*)d_in[9];
    const float* Whh2 = (const float*)d_in[10];
    const float* bih2 = (const float*)d_in[11];
    const float* bhh2 = (const float*)d_in[12];
    const float* fc1w = (const float*)d_in[13];
    const float* fc1b = (const float*)d_in[14];
    const float* fc2w = (const float*)d_in[15];
    const float* fc2b = (const float*)d_in[16];
    float* out = (float*)d_out;

    cudaFuncSetAttribute(rnn_fused_kernel,
                         cudaFuncAttributeMaxDynamicSharedMemorySize, SMEM_BYTES);

    rnn_fused_kernel<<<NBLOCKS, NTHREADS, SMEM_BYTES>>>(
        x, Wih0, Whh0, bih0, bhh0,
        Wih1, Whh1, bih1, bhh1,
        Wih2, Whh2, bih2, bhh2,
        fc1w, fc1b, fc2w, fc2b, out);
}